// round 5
// baseline (speedup 1.0000x reference)
#include <cuda_runtime.h>
#include <math.h>

#define NMAX   (1 << 20)
#define NBMAX  ((NMAX + 127) / 128)
#define NB2MAX ((NBMAX + 127) / 128)
#define STATS_BLOCKS 1024

typedef unsigned long long ull;

// -------- scratch ----------
__device__ float4   g_feat4[16 * NMAX];             // packed xyz_feat [16][N] float4
__device__ float    g_out_part[(size_t)NBMAX * 256];
__device__ float    g_out_part2[(size_t)NB2MAX * 256];
__device__ float    g_stats_part[STATS_BLOCKS * 12];
__device__ float    g_norm[4];
__device__ unsigned g_glb[64];

// -------- f32x2 helpers ----------
__device__ __forceinline__ ull pack2(float lo, float hi) {
    ull r; asm("mov.b64 %0, {%1,%2};" : "=l"(r) : "f"(lo), "f"(hi)); return r;
}
__device__ __forceinline__ void unpack2(ull v, float& lo, float& hi) {
    asm("mov.b64 {%0,%1}, %2;" : "=f"(lo), "=f"(hi) : "l"(v));
}
__device__ __forceinline__ ull ffma2(ull a, ull b, ull c) {
    ull d; asm("fma.rn.f32x2 %0, %1, %2, %3;" : "=l"(d) : "l"(a), "l"(b), "l"(c));
    return d;
}

__device__ __forceinline__ unsigned enc_f(float f) {
    unsigned u = __float_as_uint(f);
    return (u & 0x80000000u) ? ~u : (u | 0x80000000u);
}
__device__ __forceinline__ float dec_f(unsigned k) {
    return (k & 0x80000000u) ? __uint_as_float(k ^ 0x80000000u)
                             : __uint_as_float(~k);
}

// LayerNorm with 16 accumulators: depth-4 chains + 4-level tree
__device__ __forceinline__ void layer_norm64(float (&x)[64], const float* g,
                                             const float* b, bool do_relu) {
    float s[16], q[16];
#pragma unroll
    for (int j = 0; j < 16; j++) {
        s[j] = (x[j] + x[j + 16]) + (x[j + 32] + x[j + 48]);
        q[j] = fmaf(x[j], x[j],
               fmaf(x[j + 16], x[j + 16],
               fmaf(x[j + 32], x[j + 32], x[j + 48] * x[j + 48])));
    }
#pragma unroll
    for (int off = 8; off > 0; off >>= 1) {
#pragma unroll
        for (int j = 0; j < off; j++) { s[j] += s[j + off]; q[j] += q[j + off]; }
    }
    float m = s[0] * (1.0f / 64.0f);
    float v = fmaf(-m, m, q[0] * (1.0f / 64.0f));
    float r = rsqrtf(fmaxf(v, 0.0f) + 1e-5f);
#pragma unroll
    for (int j = 0; j < 64; j++) {
        float t = (x[j] - m) * r;
        float y = fmaf(t, g[j], b[j]);
        x[j] = do_relu ? fmaxf(y, 0.0f) : y;
    }
}

// inner step of the packed GEMV: o2 += xk * W[k][:]
__device__ __forceinline__ void gemv_step(float xk, const float* s_w_row,
                                          ull (&o2)[32]) {
    ull xk2 = pack2(xk, xk);
    const ulonglong2* wr = (const ulonglong2*)s_w_row;
#pragma unroll
    for (int jv = 0; jv < 16; jv++) {
        ulonglong2 w = wr[jv];
        o2[2 * jv + 0] = ffma2(xk2, w.x, o2[2 * jv + 0]);
        o2[2 * jv + 1] = ffma2(xk2, w.y, o2[2 * jv + 1]);
    }
}

// -------- kernel 1: per-block xyz stats ------------------------------------
__global__ void k_stats(const float* __restrict__ xyz, int n) {
    float mn0 =  INFINITY, mn1 =  INFINITY, mn2 =  INFINITY;
    float mx0 = -INFINITY, mx1 = -INFINITY, mx2 = -INFINITY;
    float s0 = 0.f, s1 = 0.f, s2 = 0.f;
    for (int i = blockIdx.x * blockDim.x + threadIdx.x; i < n;
         i += gridDim.x * blockDim.x) {
        float x0 = xyz[3 * i + 0], x1 = xyz[3 * i + 1], x2 = xyz[3 * i + 2];
        mn0 = fminf(mn0, x0); mn1 = fminf(mn1, x1); mn2 = fminf(mn2, x2);
        mx0 = fmaxf(mx0, x0); mx1 = fmaxf(mx1, x1); mx2 = fmaxf(mx2, x2);
        s0 += x0; s1 += x1; s2 += x2;
    }
#pragma unroll
    for (int o = 16; o > 0; o >>= 1) {
        mn0 = fminf(mn0, __shfl_xor_sync(0xffffffffu, mn0, o));
        mn1 = fminf(mn1, __shfl_xor_sync(0xffffffffu, mn1, o));
        mn2 = fminf(mn2, __shfl_xor_sync(0xffffffffu, mn2, o));
        mx0 = fmaxf(mx0, __shfl_xor_sync(0xffffffffu, mx0, o));
        mx1 = fmaxf(mx1, __shfl_xor_sync(0xffffffffu, mx1, o));
        mx2 = fmaxf(mx2, __shfl_xor_sync(0xffffffffu, mx2, o));
        s0 += __shfl_xor_sync(0xffffffffu, s0, o);
        s1 += __shfl_xor_sync(0xffffffffu, s1, o);
        s2 += __shfl_xor_sync(0xffffffffu, s2, o);
    }
    __shared__ float sh[8][9];
    int wid = threadIdx.x >> 5, lane = threadIdx.x & 31;
    if (lane == 0) {
        sh[wid][0] = mn0; sh[wid][1] = mn1; sh[wid][2] = mn2;
        sh[wid][3] = mx0; sh[wid][4] = mx1; sh[wid][5] = mx2;
        sh[wid][6] = s0;  sh[wid][7] = s1;  sh[wid][8] = s2;
    }
    __syncthreads();
    if (threadIdx.x == 0) {
        float r[9];
#pragma unroll
        for (int q = 0; q < 9; q++) r[q] = sh[0][q];
        for (int w = 1; w < 8; w++) {
            r[0] = fminf(r[0], sh[w][0]); r[1] = fminf(r[1], sh[w][1]);
            r[2] = fminf(r[2], sh[w][2]);
            r[3] = fmaxf(r[3], sh[w][3]); r[4] = fmaxf(r[4], sh[w][4]);
            r[5] = fmaxf(r[5], sh[w][5]);
            r[6] += sh[w][6]; r[7] += sh[w][7]; r[8] += sh[w][8];
        }
#pragma unroll
        for (int q = 0; q < 9; q++) g_stats_part[blockIdx.x * 12 + q] = r[q];
    }
}

// -------- kernel 2: finalize stats + init glb ------------------------------
__global__ void k_stats_final(int n) {
    int tid = threadIdx.x;
    float mn0 =  INFINITY, mn1 =  INFINITY, mn2 =  INFINITY;
    float mx0 = -INFINITY, mx1 = -INFINITY, mx2 = -INFINITY;
    float s0 = 0.f, s1 = 0.f, s2 = 0.f;
    for (int p = tid; p < STATS_BLOCKS; p += 256) {
        const float* r = &g_stats_part[p * 12];
        mn0 = fminf(mn0, r[0]); mn1 = fminf(mn1, r[1]); mn2 = fminf(mn2, r[2]);
        mx0 = fmaxf(mx0, r[3]); mx1 = fmaxf(mx1, r[4]); mx2 = fmaxf(mx2, r[5]);
        s0 += r[6]; s1 += r[7]; s2 += r[8];
    }
#pragma unroll
    for (int o = 16; o > 0; o >>= 1) {
        mn0 = fminf(mn0, __shfl_xor_sync(0xffffffffu, mn0, o));
        mn1 = fminf(mn1, __shfl_xor_sync(0xffffffffu, mn1, o));
        mn2 = fminf(mn2, __shfl_xor_sync(0xffffffffu, mn2, o));
        mx0 = fmaxf(mx0, __shfl_xor_sync(0xffffffffu, mx0, o));
        mx1 = fmaxf(mx1, __shfl_xor_sync(0xffffffffu, mx1, o));
        mx2 = fmaxf(mx2, __shfl_xor_sync(0xffffffffu, mx2, o));
        s0 += __shfl_xor_sync(0xffffffffu, s0, o);
        s1 += __shfl_xor_sync(0xffffffffu, s1, o);
        s2 += __shfl_xor_sync(0xffffffffu, s2, o);
    }
    __shared__ float sh[8][9];
    int wid = tid >> 5, lane = tid & 31;
    if (lane == 0) {
        sh[wid][0] = mn0; sh[wid][1] = mn1; sh[wid][2] = mn2;
        sh[wid][3] = mx0; sh[wid][4] = mx1; sh[wid][5] = mx2;
        sh[wid][6] = s0;  sh[wid][7] = s1;  sh[wid][8] = s2;
    }
    __syncthreads();
    if (tid == 0) {
        float r[9];
#pragma unroll
        for (int q = 0; q < 9; q++) r[q] = sh[0][q];
        for (int w = 1; w < 8; w++) {
            r[0] = fminf(r[0], sh[w][0]); r[1] = fminf(r[1], sh[w][1]);
            r[2] = fminf(r[2], sh[w][2]);
            r[3] = fmaxf(r[3], sh[w][3]); r[4] = fmaxf(r[4], sh[w][4]);
            r[5] = fmaxf(r[5], sh[w][5]);
            r[6] += sh[w][6]; r[7] += sh[w][7]; r[8] += sh[w][8];
        }
        float inv_n = 1.0f / (float)n;
        float dia = fmaxf(fmaxf(r[3] - r[0], r[4] - r[1]), r[5] - r[2]);
        g_norm[0] = r[6] * inv_n;
        g_norm[1] = r[7] * inv_n;
        g_norm[2] = r[8] * inv_n;
        g_norm[3] = 1.0f / (dia + 0.0001f);
    }
    if (tid < 64) g_glb[tid] = 0u;
}

// -------- kernel 3: phase 1 (128 threads; h[0:32] staged to smem) -----------
__global__ void __launch_bounds__(128)
k_phase1(const float* __restrict__ xyz,
         const float* __restrict__ w1, const float* __restrict__ b1,
         const float* __restrict__ ln1g, const float* __restrict__ ln1b,
         const float* __restrict__ w2, const float* __restrict__ b2,
         const float* __restrict__ ln2g, const float* __restrict__ ln2b,
         int n) {
    __shared__ __align__(16) float s_w2[4096];
    __shared__ float s_x[32][128];            // staged h[0:32], own-column
    __shared__ __align__(16) float s_b2[64];
    __shared__ float s_w1[192], s_b1[64], s_ln1g[64], s_ln1b[64];
    __shared__ float s_ln2g[64], s_ln2b[64];
    __shared__ float s_norm[4];
    __shared__ unsigned s_glb[64];

    int tid = threadIdx.x;
    for (int q = tid; q < 4096; q += 128) s_w2[q] = w2[q];
    if (tid < 64) {
        s_w1[tid] = w1[tid]; s_w1[64 + tid] = w1[64 + tid];
        s_w1[128 + tid] = w1[128 + tid];
        s_b1[tid] = b1[tid]; s_ln1g[tid] = ln1g[tid]; s_ln1b[tid] = ln1b[tid];
        s_b2[tid] = b2[tid]; s_ln2g[tid] = ln2g[tid]; s_ln2b[tid] = ln2b[tid];
        s_glb[tid] = 0u;
    }
    if (tid < 4) s_norm[tid] = g_norm[tid];
    __syncthreads();

    int i = blockIdx.x * 128 + tid;
    bool valid = (i < n);
    float x0 = 0.f, x1 = 0.f, x2 = 0.f;
    if (valid) {
        float scale = s_norm[3];
        x0 = (xyz[3 * i + 0] - s_norm[0]) * scale;
        x1 = (xyz[3 * i + 1] - s_norm[1]) * scale;
        x2 = (xyz[3 * i + 2] - s_norm[2]) * scale;
    }

    float h[64];
#pragma unroll
    for (int j = 0; j < 64; j++)
        h[j] = fmaf(x2, s_w1[128 + j], fmaf(x1, s_w1[64 + j], fmaf(x0, s_w1[j], s_b1[j])));
    layer_norm64(h, s_ln1g, s_ln1b, true);

    // stage first half to smem (own column; no cross-thread sharing -> no sync)
#pragma unroll
    for (int k = 0; k < 32; k++) s_x[k][tid] = h[k];
    float hh[32];
#pragma unroll
    for (int k = 0; k < 32; k++) hh[k] = h[32 + k];

    ull o2[32];
    const ull* b2p = (const ull*)s_b2;
#pragma unroll
    for (int jv = 0; jv < 32; jv++) o2[jv] = b2p[jv];
#pragma unroll
    for (int k = 0; k < 32; k++) gemv_step(s_x[k][tid], s_w2 + k * 64, o2);
#pragma unroll
    for (int k = 0; k < 32; k++) gemv_step(hh[k], s_w2 + (32 + k) * 64, o2);

    float o[64];
#pragma unroll
    for (int jv = 0; jv < 32; jv++) unpack2(o2[jv], o[2 * jv], o[2 * jv + 1]);
    layer_norm64(o, s_ln2g, s_ln2b, false);

    if (valid) {
#pragma unroll
        for (int k4 = 0; k4 < 16; k4++) {
            float4 v = make_float4(o[4 * k4], o[4 * k4 + 1],
                                   o[4 * k4 + 2], o[4 * k4 + 3]);
            g_feat4[(size_t)k4 * n + i] = v;
        }
    }

    int lane = tid & 31;
#pragma unroll
    for (int j = 0; j < 64; j++) {
        float v = valid ? o[j] : -INFINITY;
#pragma unroll
        for (int off = 16; off > 0; off >>= 1)
            v = fmaxf(v, __shfl_xor_sync(0xffffffffu, v, off));
        if (lane == 0) atomicMax(&s_glb[j], enc_f(v));
    }
    __syncthreads();
    if (tid < 64) atomicMax(&g_glb[tid], s_glb[tid]);
}

// -------- kernel 4: phase 2 (glb-fold inlined; streams f via float4) ---------
__global__ void __launch_bounds__(128)
k_phase2(const float* __restrict__ feat,
         const float* __restrict__ w3, const float* __restrict__ b3,
         const float* __restrict__ ln3g, const float* __restrict__ ln3b,
         const float* __restrict__ w4, int n) {
    __shared__ __align__(16) float s_w3[8192];   // full w3 (both halves)
    __shared__ __align__(16) float s_gc[64];
    __shared__ float s_glbv[64];
    __shared__ float s_ln3g[64], s_ln3b[64], s_w4[64];
    __shared__ float s_w[128];
    __shared__ float4 s_part[2][64];

    int tid = threadIdx.x;
    for (int q = tid; q < 8192; q += 128) s_w3[q] = w3[q];
    if (tid < 64) {
        s_glbv[tid] = dec_f(g_glb[tid]);
        s_ln3g[tid] = ln3g[tid]; s_ln3b[tid] = ln3b[tid];
        s_w4[tid] = w4[tid];
    }
    __syncthreads();

    // fold glb into bias: s_gc[j] = b3[j] + sum_k glb[k] * w3[64+k][j]
    if (tid < 64) {
        int j = tid;
        float a0 = b3[j], a1 = 0.f, a2 = 0.f, a3 = 0.f;
#pragma unroll
        for (int k = 0; k < 64; k += 4) {
            a0 = fmaf(s_glbv[k + 0], s_w3[(64 + k + 0) * 64 + j], a0);
            a1 = fmaf(s_glbv[k + 1], s_w3[(64 + k + 1) * 64 + j], a1);
            a2 = fmaf(s_glbv[k + 2], s_w3[(64 + k + 2) * 64 + j], a2);
            a3 = fmaf(s_glbv[k + 3], s_w3[(64 + k + 3) * 64 + j], a3);
        }
        s_gc[j] = (a0 + a1) + (a2 + a3);
    }
    __syncthreads();

    int i = blockIdx.x * 128 + tid;
    int iload = (i < n) ? i : (n - 1);   // clamp; invalid lanes discarded later

    ull o2[32];
    const ull* gcp = (const ull*)s_gc;
#pragma unroll
    for (int jv = 0; jv < 32; jv++) o2[jv] = gcp[jv];

    // GEMV with f streamed from gmem as float4, two batches of 8 (MLP=8x16B)
#pragma unroll
    for (int half = 0; half < 2; half++) {
        float4 fr[8];
#pragma unroll
        for (int q = 0; q < 8; q++)
            fr[q] = g_feat4[(size_t)(half * 8 + q) * n + iload];
#pragma unroll
        for (int q = 0; q < 8; q++) {
            int kb = (half * 8 + q) * 4;
            gemv_step(fr[q].x, s_w3 + (kb + 0) * 64, o2);
            gemv_step(fr[q].y, s_w3 + (kb + 1) * 64, o2);
            gemv_step(fr[q].z, s_w3 + (kb + 2) * 64, o2);
            gemv_step(fr[q].w, s_w3 + (kb + 3) * 64, o2);
        }
    }

    float o[64];
#pragma unroll
    for (int jv = 0; jv < 32; jv++) unpack2(o2[jv], o[2 * jv], o[2 * jv + 1]);
    layer_norm64(o, s_ln3g, s_ln3b, true);

    // logit dot: 16-acc tree
    float t[16];
#pragma unroll
    for (int j = 0; j < 16; j++)
        t[j] = fmaf(o[j], s_w4[j],
               fmaf(o[j + 16], s_w4[j + 16],
               fmaf(o[j + 32], s_w4[j + 32], o[j + 48] * s_w4[j + 48])));
#pragma unroll
    for (int off = 8; off > 0; off >>= 1) {
#pragma unroll
        for (int j = 0; j < off; j++) t[j] += t[j + off];
    }
    float wv = (i < n) ? (2.0f / (1.0f + __expf(-t[0]))) : 0.f;
    s_w[tid] = wv;
    __syncthreads();

    // feat accumulation: 2 row-groups x 64 float4 columns (D == 256)
    int c = tid & 63;
    int g = tid >> 6;
    const float4* fp = (const float4*)feat;
    float4 acc = make_float4(0.f, 0.f, 0.f, 0.f);
    int rbase = blockIdx.x * 128 + g * 64;
    if (rbase + 64 <= n) {
#pragma unroll 8
        for (int ii = 0; ii < 64; ii++) {
            float4 v = fp[(size_t)(rbase + ii) * 64 + c];
            float ww = s_w[g * 64 + ii];
            acc.x = fmaf(v.x, ww, acc.x);
            acc.y = fmaf(v.y, ww, acc.y);
            acc.z = fmaf(v.z, ww, acc.z);
            acc.w = fmaf(v.w, ww, acc.w);
        }
    } else {
#pragma unroll 8
        for (int ii = 0; ii < 64; ii++) {
            int r = rbase + ii;
            if (r < n) {
                float4 v = fp[(size_t)r * 64 + c];
                float ww = s_w[g * 64 + ii];
                acc.x = fmaf(v.x, ww, acc.x);
                acc.y = fmaf(v.y, ww, acc.y);
                acc.z = fmaf(v.z, ww, acc.z);
                acc.w = fmaf(v.w, ww, acc.w);
            }
        }
    }
    s_part[g][c] = acc;
    __syncthreads();

    if (tid < 64) {
        float4 a = s_part[0][tid];
        float4 b = s_part[1][tid];
        float4 r;
        r.x = a.x + b.x; r.y = a.y + b.y; r.z = a.z + b.z; r.w = a.w + b.w;
        ((float4*)g_out_part)[(size_t)blockIdx.x * 64 + tid] = r;
    }
}

// -------- kernel 5: mid reduction ------------------------------------------
__global__ void k_out_mid(int nb) {
    int b0 = blockIdx.x * 128;
    int bmax = nb - b0; if (bmax > 128) bmax = 128;
    int d = threadIdx.x;  // 256
    float a0 = 0.f, a1 = 0.f, a2 = 0.f, a3 = 0.f;
    int b = 0;
    for (; b + 4 <= bmax; b += 4) {
        a0 += g_out_part[(size_t)(b0 + b + 0) * 256 + d];
        a1 += g_out_part[(size_t)(b0 + b + 1) * 256 + d];
        a2 += g_out_part[(size_t)(b0 + b + 2) * 256 + d];
        a3 += g_out_part[(size_t)(b0 + b + 3) * 256 + d];
    }
    for (; b < bmax; b++)
        a0 += g_out_part[(size_t)(b0 + b) * 256 + d];
    g_out_part2[(size_t)blockIdx.x * 256 + d] = (a0 + a1) + (a2 + a3);
}

// -------- kernel 6: final ---------------------------------------------------
__global__ void k_out_final(float* __restrict__ out, int n, int nb2) {
    int d = threadIdx.x;
    float inv_n = 1.0f / (float)n;
    float s = 0.f;
    for (int b = 0; b < nb2; b++) s += g_out_part2[(size_t)b * 256 + d];
    out[d] = s * inv_n;
}

// -------- launch ------------------------------------------------------------
extern "C" void kernel_launch(void* const* d_in, const int* in_sizes, int n_in,
                              void* d_out, int out_size) {
    const float* feat = (const float*)d_in[0];
    const float* xyz  = (const float*)d_in[1];
    const float* w1   = (const float*)d_in[2];
    const float* b1   = (const float*)d_in[3];
    const float* ln1g = (const float*)d_in[4];
    const float* ln1b = (const float*)d_in[5];
    const float* w2   = (const float*)d_in[6];
    const float* b2   = (const float*)d_in[7];
    const float* ln2g = (const float*)d_in[8];
    const float* ln2b = (const float*)d_in[9];
    const float* w3   = (const float*)d_in[10];
    const float* b3   = (const float*)d_in[11];
    const float* ln3g = (const float*)d_in[12];
    const float* ln3b = (const float*)d_in[13];
    const float* w4   = (const float*)d_in[14];

    int n = in_sizes[1] / 3;
    int NB = (n + 127) / 128;
    int NB2 = (NB + 127) / 128;

    k_stats<<<STATS_BLOCKS, 256>>>(xyz, n);
    k_stats_final<<<1, 256>>>(n);
    k_phase1<<<NB, 128>>>(xyz, w1, b1, ln1g, ln1b, w2, b2, ln2g, ln2b, n);
    k_phase2<<<NB, 128>>>(feat, w3, b3, ln3g, ln3b, w4, n);
    k_out_mid<<<NB2, 256>>>(NB);
    k_out_final<<<1, 256>>>((float*)d_out, n, NB2);
}

// round 7
// speedup vs baseline: 2.0057x; 2.0057x over previous
#include <cuda_runtime.h>
#include <cuda_bf16.h>
#include <math.h>
#include <cstdint>

#define NMAX   (1 << 20)
#define NBMAX  ((NMAX + 127) / 128)
#define NB2MAX ((NBMAX + 127) / 128)
#define STATS_BLOCKS 1024

// -------- scratch (xyz_feat stored as pre-packed MMA A-fragments) ----------
__device__ uint4    g_scr_hi[(size_t)8 * NMAX];
__device__ uint4    g_scr_lo[(size_t)8 * NMAX];
__device__ float    g_out_part[(size_t)NBMAX * 256];
__device__ float    g_out_part2[(size_t)NB2MAX * 256];
__device__ float    g_stats_part[STATS_BLOCKS * 12];
__device__ float    g_norm[4];
__device__ unsigned g_glb[64];

// -------- low-level helpers ----------
__device__ __forceinline__ uint32_t smem_u32(const void* p) {
    uint32_t a;
    asm("{ .reg .u64 t; cvta.to.shared.u64 t, %1; cvt.u32.u64 %0, t; }"
        : "=r"(a) : "l"(p));
    return a;
}
__device__ __forceinline__ void ldsm_x4(uint32_t (&r)[4], uint32_t a) {
    asm volatile("ldmatrix.sync.aligned.m8n8.x4.shared.b16 {%0,%1,%2,%3}, [%4];"
                 : "=r"(r[0]), "=r"(r[1]), "=r"(r[2]), "=r"(r[3]) : "r"(a));
}
__device__ __forceinline__ void ldsm_x2t(uint32_t (&r)[2], uint32_t a) {
    asm volatile("ldmatrix.sync.aligned.m8n8.x2.trans.shared.b16 {%0,%1}, [%2];"
                 : "=r"(r[0]), "=r"(r[1]) : "r"(a));
}
__device__ __forceinline__ void mma16816(float (&d)[4], const uint32_t (&a)[4],
                                         const uint32_t (&b)[2]) {
    asm volatile(
        "mma.sync.aligned.m16n8k16.row.col.f32.bf16.bf16.f32 "
        "{%0,%1,%2,%3}, {%4,%5,%6,%7}, {%8,%9}, {%0,%1,%2,%3};"
        : "+f"(d[0]), "+f"(d[1]), "+f"(d[2]), "+f"(d[3])
        : "r"(a[0]), "r"(a[1]), "r"(a[2]), "r"(a[3]), "r"(b[0]), "r"(b[1]));
}

__device__ __forceinline__ void split2(float a, float b, uint32_t& hi, uint32_t& lo) {
    __nv_bfloat16 ah = __float2bfloat16_rn(a), bh = __float2bfloat16_rn(b);
    float ar = a - __bfloat162float(ah);
    float br = b - __bfloat162float(bh);
    __nv_bfloat16 al = __float2bfloat16_rn(ar), bl = __float2bfloat16_rn(br);
    hi = ((uint32_t)__bfloat16_as_ushort(bh) << 16) | __bfloat16_as_ushort(ah);
    lo = ((uint32_t)__bfloat16_as_ushort(bl) << 16) | __bfloat16_as_ushort(al);
}

__device__ __forceinline__ unsigned enc_f(float f) {
    unsigned u = __float_as_uint(f);
    return (u & 0x80000000u) ? ~u : (u | 0x80000000u);
}
__device__ __forceinline__ float dec_f(unsigned k) {
    return (k & 0x80000000u) ? __uint_as_float(k ^ 0x80000000u)
                             : __uint_as_float(~k);
}

#define SWZ(b) ((b) ^ (((b) >> 3) & 0x70))

// thread-domain LayerNorm (for LN1 where h lives in one thread)
__device__ __forceinline__ void layer_norm64(float (&x)[64], const float* g,
                                             const float* b, bool do_relu) {
    float s[16], q[16];
#pragma unroll
    for (int j = 0; j < 16; j++) {
        s[j] = (x[j] + x[j + 16]) + (x[j + 32] + x[j + 48]);
        q[j] = fmaf(x[j], x[j],
               fmaf(x[j + 16], x[j + 16],
               fmaf(x[j + 32], x[j + 32], x[j + 48] * x[j + 48])));
    }
#pragma unroll
    for (int off = 8; off > 0; off >>= 1) {
#pragma unroll
        for (int j = 0; j < off; j++) { s[j] += s[j + off]; q[j] += q[j + off]; }
    }
    float m = s[0] * (1.0f / 64.0f);
    float v = fmaf(-m, m, q[0] * (1.0f / 64.0f));
    float r = rsqrtf(fmaxf(v, 0.0f) + 1e-5f);
#pragma unroll
    for (int j = 0; j < 64; j++) {
        float t = (x[j] - m) * r;
        float y = fmaf(t, g[j], b[j]);
        x[j] = do_relu ? fmaxf(y, 0.0f) : y;
    }
}

// fragment-domain LayerNorm over the 4-lane quad
__device__ __forceinline__ void ln_frag(float (&acc)[2][8][4],
                                        const float2 (&g2)[8],
                                        const float2 (&b2)[8], bool do_relu) {
#pragma unroll
    for (int mt = 0; mt < 2; mt++) {
#pragma unroll
        for (int hh = 0; hh < 2; hh++) {
            float s = 0.f, q = 0.f;
#pragma unroll
            for (int nn = 0; nn < 8; nn++) {
                float v0 = acc[mt][nn][2 * hh], v1 = acc[mt][nn][2 * hh + 1];
                s += v0 + v1;
                q = fmaf(v0, v0, fmaf(v1, v1, q));
            }
            s += __shfl_xor_sync(0xffffffffu, s, 1);
            s += __shfl_xor_sync(0xffffffffu, s, 2);
            q += __shfl_xor_sync(0xffffffffu, q, 1);
            q += __shfl_xor_sync(0xffffffffu, q, 2);
            float m = s * (1.0f / 64.0f);
            float var = fmaf(-m, m, q * (1.0f / 64.0f));
            float r = rsqrtf(fmaxf(var, 0.0f) + 1e-5f);
#pragma unroll
            for (int nn = 0; nn < 8; nn++) {
                float y0 = fmaf((acc[mt][nn][2 * hh] - m) * r, g2[nn].x, b2[nn].x);
                float y1 = fmaf((acc[mt][nn][2 * hh + 1] - m) * r, g2[nn].y, b2[nn].y);
                acc[mt][nn][2 * hh] = do_relu ? fmaxf(y0, 0.f) : y0;
                acc[mt][nn][2 * hh + 1] = do_relu ? fmaxf(y1, 0.f) : y1;
            }
        }
    }
}

// build split-bf16 B planes (row = k, 64 rows x 128B) from fp32 stage[k*64+n]
__device__ __forceinline__ void build_B(char* sm, int offhi, int offlo,
                                        const float* stage, int tid) {
#pragma unroll
    for (int it = 0; it < 16; it++) {
        int idx = it * 128 + tid;
        int np = idx & 31, k = idx >> 5;
        float v0 = stage[k * 64 + 2 * np];
        float v1 = stage[k * 64 + 2 * np + 1];
        uint32_t hp, lp;
        split2(v0, v1, hp, lp);
        int byte = k * 128 + np * 4;
        int sw = SWZ(byte);
        *(uint32_t*)(sm + offhi + sw) = hp;
        *(uint32_t*)(sm + offlo + sw) = lp;
    }
}

__device__ __forceinline__ uint32_t a_addr(uint32_t base, int w, int mt, int ks,
                                           int lane) {
    int row = 32 * w + 16 * mt + (lane & 7) + (lane & 8);
    int byte = row * 128 + ks * 32 + ((lane & 16) ? 16 : 0);
    return base + SWZ(byte);
}
__device__ __forceinline__ uint32_t b_addr(uint32_t base, int ks, int nn, int lane) {
    int k = ks * 16 + (lane & 7) + (lane & 8);
    int byte = k * 128 + nn * 16;
    return base + SWZ(byte);
}

// -------- kernel 1: per-block xyz stats ------------------------------------
__global__ void k_stats(const float* __restrict__ xyz, int n) {
    float mn0 =  INFINITY, mn1 =  INFINITY, mn2 =  INFINITY;
    float mx0 = -INFINITY, mx1 = -INFINITY, mx2 = -INFINITY;
    float s0 = 0.f, s1 = 0.f, s2 = 0.f;
    for (int i = blockIdx.x * blockDim.x + threadIdx.x; i < n;
         i += gridDim.x * blockDim.x) {
        float x0 = xyz[3 * i + 0], x1 = xyz[3 * i + 1], x2 = xyz[3 * i + 2];
        mn0 = fminf(mn0, x0); mn1 = fminf(mn1, x1); mn2 = fminf(mn2, x2);
        mx0 = fmaxf(mx0, x0); mx1 = fmaxf(mx1, x1); mx2 = fmaxf(mx2, x2);
        s0 += x0; s1 += x1; s2 += x2;
    }
#pragma unroll
    for (int o = 16; o > 0; o >>= 1) {
        mn0 = fminf(mn0, __shfl_xor_sync(0xffffffffu, mn0, o));
        mn1 = fminf(mn1, __shfl_xor_sync(0xffffffffu, mn1, o));
        mn2 = fminf(mn2, __shfl_xor_sync(0xffffffffu, mn2, o));
        mx0 = fmaxf(mx0, __shfl_xor_sync(0xffffffffu, mx0, o));
        mx1 = fmaxf(mx1, __shfl_xor_sync(0xffffffffu, mx1, o));
        mx2 = fmaxf(mx2, __shfl_xor_sync(0xffffffffu, mx2, o));
        s0 += __shfl_xor_sync(0xffffffffu, s0, o);
        s1 += __shfl_xor_sync(0xffffffffu, s1, o);
        s2 += __shfl_xor_sync(0xffffffffu, s2, o);
    }
    __shared__ float sh[8][9];
    int wid = threadIdx.x >> 5, lane = threadIdx.x & 31;
    if (lane == 0) {
        sh[wid][0] = mn0; sh[wid][1] = mn1; sh[wid][2] = mn2;
        sh[wid][3] = mx0; sh[wid][4] = mx1; sh[wid][5] = mx2;
        sh[wid][6] = s0;  sh[wid][7] = s1;  sh[wid][8] = s2;
    }
    __syncthreads();
    if (threadIdx.x == 0) {
        float r[9];
#pragma unroll
        for (int q = 0; q < 9; q++) r[q] = sh[0][q];
        for (int w = 1; w < 8; w++) {
            r[0] = fminf(r[0], sh[w][0]); r[1] = fminf(r[1], sh[w][1]);
            r[2] = fminf(r[2], sh[w][2]);
            r[3] = fmaxf(r[3], sh[w][3]); r[4] = fmaxf(r[4], sh[w][4]);
            r[5] = fmaxf(r[5], sh[w][5]);
            r[6] += sh[w][6]; r[7] += sh[w][7]; r[8] += sh[w][8];
        }
#pragma unroll
        for (int q = 0; q < 9; q++) g_stats_part[blockIdx.x * 12 + q] = r[q];
    }
}

// -------- kernel 2: finalize stats + init glb ------------------------------
__global__ void k_stats_final(int n) {
    int tid = threadIdx.x;
    float mn0 =  INFINITY, mn1 =  INFINITY, mn2 =  INFINITY;
    float mx0 = -INFINITY, mx1 = -INFINITY, mx2 = -INFINITY;
    float s0 = 0.f, s1 = 0.f, s2 = 0.f;
    for (int p = tid; p < STATS_BLOCKS; p += 256) {
        const float* r = &g_stats_part[p * 12];
        mn0 = fminf(mn0, r[0]); mn1 = fminf(mn1, r[1]); mn2 = fminf(mn2, r[2]);
        mx0 = fmaxf(mx0, r[3]); mx1 = fmaxf(mx1, r[4]); mx2 = fmaxf(mx2, r[5]);
        s0 += r[6]; s1 += r[7]; s2 += r[8];
    }
#pragma unroll
    for (int o = 16; o > 0; o >>= 1) {
        mn0 = fminf(mn0, __shfl_xor_sync(0xffffffffu, mn0, o));
        mn1 = fminf(mn1, __shfl_xor_sync(0xffffffffu, mn1, o));
        mn2 = fminf(mn2, __shfl_xor_sync(0xffffffffu, mn2, o));
        mx0 = fmaxf(mx0, __shfl_xor_sync(0xffffffffu, mx0, o));
        mx1 = fmaxf(mx1, __shfl_xor_sync(0xffffffffu, mx1, o));
        mx2 = fmaxf(mx2, __shfl_xor_sync(0xffffffffu, mx2, o));
        s0 += __shfl_xor_sync(0xffffffffu, s0, o);
        s1 += __shfl_xor_sync(0xffffffffu, s1, o);
        s2 += __shfl_xor_sync(0xffffffffu, s2, o);
    }
    __shared__ float sh[8][9];
    int wid = tid >> 5, lane = tid & 31;
    if (lane == 0) {
        sh[wid][0] = mn0; sh[wid][1] = mn1; sh[wid][2] = mn2;
        sh[wid][3] = mx0; sh[wid][4] = mx1; sh[wid][5] = mx2;
        sh[wid][6] = s0;  sh[wid][7] = s1;  sh[wid][8] = s2;
    }
    __syncthreads();
    if (tid == 0) {
        float r[9];
#pragma unroll
        for (int q = 0; q < 9; q++) r[q] = sh[0][q];
        for (int w = 1; w < 8; w++) {
            r[0] = fminf(r[0], sh[w][0]); r[1] = fminf(r[1], sh[w][1]);
            r[2] = fminf(r[2], sh[w][2]);
            r[3] = fmaxf(r[3], sh[w][3]); r[4] = fmaxf(r[4], sh[w][4]);
            r[5] = fmaxf(r[5], sh[w][5]);
            r[6] += sh[w][6]; r[7] += sh[w][7]; r[8] += sh[w][8];
        }
        float inv_n = 1.0f / (float)n;
        float dia = fmaxf(fmaxf(r[3] - r[0], r[4] - r[1]), r[5] - r[2]);
        g_norm[0] = r[6] * inv_n;
        g_norm[1] = r[7] * inv_n;
        g_norm[2] = r[8] * inv_n;
        g_norm[3] = 1.0f / (dia + 0.0001f);
    }
    if (tid < 64) g_glb[tid] = 0u;
}

// ---- phase1 smem layout ----
#define OFF_A_HI 0
#define OFF_A_LO 16384
#define P1_B_HI  32768
#define P1_B_LO  40960
#define P1_W1    49152
#define P1_B1    49920
#define P1_LN1G  50176
#define P1_LN1B  50432
#define P1_B2    50688
#define P1_LN2G  50944
#define P1_LN2B  51200
#define P1_NORM  51456
#define P1_GLB   51472
#define P1_DSM   51728
// ---- phase2 smem layout ----
#define P2_STAGE 0
#define P2_B_HI  16384
#define P2_B_LO  24576
#define P2_GC    32768
#define P2_GLBV  33024
#define P2_LN3G  33280
#define P2_LN3B  33536
#define P2_W4    33792
#define P2_SW    34048
#define P2_SPART 34560
#define P2_DSM   36608

// -------- kernel 3: phase 1 --------------------------------------------------
__global__ void __launch_bounds__(128)
k_phase1(const float* __restrict__ xyz,
         const float* __restrict__ w1, const float* __restrict__ b1,
         const float* __restrict__ ln1g, const float* __restrict__ ln1b,
         const float* __restrict__ w2, const float* __restrict__ b2,
         const float* __restrict__ ln2g, const float* __restrict__ ln2b,
         int n) {
    extern __shared__ __align__(1024) char sm[];
    int tid = threadIdx.x, w = tid >> 5, lane = tid & 31, c = lane & 3;
    uint32_t smu = smem_u32(sm);

    float* stage = (float*)(sm + OFF_A_HI);       // w2 fp32 staged in A region
    for (int q = tid; q < 4096; q += 128) stage[q] = w2[q];
    if (tid < 64) {
        ((float*)(sm + P1_W1))[tid]       = w1[tid];
        ((float*)(sm + P1_W1))[64 + tid]  = w1[64 + tid];
        ((float*)(sm + P1_W1))[128 + tid] = w1[128 + tid];
        ((float*)(sm + P1_B1))[tid]   = b1[tid];
        ((float*)(sm + P1_LN1G))[tid] = ln1g[tid];
        ((float*)(sm + P1_LN1B))[tid] = ln1b[tid];
        ((float*)(sm + P1_B2))[tid]   = b2[tid];
        ((float*)(sm + P1_LN2G))[tid] = ln2g[tid];
        ((float*)(sm + P1_LN2B))[tid] = ln2b[tid];
        ((unsigned*)(sm + P1_GLB))[tid] = 0u;
    }
    if (tid < 4) ((float*)(sm + P1_NORM))[tid] = g_norm[tid];
    __syncthreads();

    build_B(sm, P1_B_HI, P1_B_LO, stage, tid);

    int i = blockIdx.x * 128 + tid;
    bool valid = (i < n);
    float x0 = 0.f, x1 = 0.f, x2 = 0.f;
    {
        const float* nm = (const float*)(sm + P1_NORM);
        if (valid) {
            float scale = nm[3];
            x0 = (xyz[3 * i + 0] - nm[0]) * scale;
            x1 = (xyz[3 * i + 1] - nm[1]) * scale;
            x2 = (xyz[3 * i + 2] - nm[2]) * scale;
        }
    }
    float h[64];
    {
        const float* sw1 = (const float*)(sm + P1_W1);
        const float* sb1 = (const float*)(sm + P1_B1);
#pragma unroll
        for (int j = 0; j < 64; j++)
            h[j] = fmaf(x2, sw1[128 + j],
                   fmaf(x1, sw1[64 + j], fmaf(x0, sw1[j], sb1[j])));
    }
    layer_norm64(h, (const float*)(sm + P1_LN1G), (const float*)(sm + P1_LN1B), true);
    __syncthreads();   // build_B stage reads complete before A overwrite

    // A planes: row = tid
#pragma unroll
    for (int c4 = 0; c4 < 8; c4++) {
        uint4 hv, lv;
        split2(h[8 * c4 + 0], h[8 * c4 + 1], hv.x, lv.x);
        split2(h[8 * c4 + 2], h[8 * c4 + 3], hv.y, lv.y);
        split2(h[8 * c4 + 4], h[8 * c4 + 5], hv.z, lv.z);
        split2(h[8 * c4 + 6], h[8 * c4 + 7], hv.w, lv.w);
        int byte = tid * 128 + c4 * 16;
        int sw = SWZ(byte);
        *(uint4*)(sm + OFF_A_HI + sw) = hv;
        *(uint4*)(sm + OFF_A_LO + sw) = lv;
    }
    __syncthreads();

    // MMA: 3 split terms x 4 k-steps x (2 m-tiles x 8 n-tiles)
    float acc[2][8][4];
#pragma unroll
    for (int mt = 0; mt < 2; mt++)
#pragma unroll
        for (int nn = 0; nn < 8; nn++)
#pragma unroll
            for (int r = 0; r < 4; r++) acc[mt][nn][r] = 0.f;

#pragma unroll
    for (int t = 0; t < 3; t++) {
        uint32_t ab = smu + ((t < 2) ? OFF_A_HI : OFF_A_LO);
        uint32_t bb = smu + ((t == 1) ? P1_B_LO : P1_B_HI);
#pragma unroll
        for (int ks = 0; ks < 4; ks++) {
            uint32_t A0[4], A1[4];
            ldsm_x4(A0, a_addr(ab, w, 0, ks, lane));
            ldsm_x4(A1, a_addr(ab, w, 1, ks, lane));
#pragma unroll
            for (int nn = 0; nn < 8; nn++) {
                uint32_t B[2];
                ldsm_x2t(B, b_addr(bb, ks, nn, lane));
                mma16816(acc[0][nn], A0, B);
                mma16816(acc[1][nn], A1, B);
            }
        }
    }

    // epilogue: +b2, LN2 (frag domain)
    float2 add2[8], g2[8], bb2[8];
    {
        const float* pb = (const float*)(sm + P1_B2);
        const float* pg = (const float*)(sm + P1_LN2G);
        const float* pbb = (const float*)(sm + P1_LN2B);
#pragma unroll
        for (int nn = 0; nn < 8; nn++) {
            int col = nn * 8 + 2 * c;
            add2[nn] = *(const float2*)&pb[col];
            g2[nn]   = *(const float2*)&pg[col];
            bb2[nn]  = *(const float2*)&pbb[col];
        }
    }
#pragma unroll
    for (int mt = 0; mt < 2; mt++)
#pragma unroll
        for (int nn = 0; nn < 8; nn++) {
            acc[mt][nn][0] += add2[nn].x; acc[mt][nn][1] += add2[nn].y;
            acc[mt][nn][2] += add2[nn].x; acc[mt][nn][3] += add2[nn].y;
        }
    ln_frag(acc, g2, bb2, false);

    // scratch store in A-fragment layout (split bf16)
    size_t sbase = ((size_t)blockIdx.x * 4 + w) * 8;
#pragma unroll
    for (int mt = 0; mt < 2; mt++)
#pragma unroll
        for (int ks = 0; ks < 4; ks++) {
            uint4 hv, lv;
            split2(acc[mt][2 * ks][0], acc[mt][2 * ks][1], hv.x, lv.x);
            split2(acc[mt][2 * ks][2], acc[mt][2 * ks][3], hv.y, lv.y);
            split2(acc[mt][2 * ks + 1][0], acc[mt][2 * ks + 1][1], hv.z, lv.z);
            split2(acc[mt][2 * ks + 1][2], acc[mt][2 * ks + 1][3], hv.w, lv.w);
            g_scr_hi[(sbase + mt * 4 + ks) * 32 + lane] = hv;
            g_scr_lo[(sbase + mt * 4 + ks) * 32 + lane] = lv;
        }

    // channel max (frag domain): rows held by lane: 32w+16mt+8h+(lane>>2)
    int rq = lane >> 2;
    int gbase = blockIdx.x * 128 + 32 * w;
    float cmx[8][2];
#pragma unroll
    for (int nn = 0; nn < 8; nn++) { cmx[nn][0] = -INFINITY; cmx[nn][1] = -INFINITY; }
#pragma unroll
    for (int mt = 0; mt < 2; mt++)
#pragma unroll
        for (int hh = 0; hh < 2; hh++) {
            bool vr = (gbase + 16 * mt + 8 * hh + rq) < n;
            if (vr) {
#pragma unroll
                for (int nn = 0; nn < 8; nn++) {
                    cmx[nn][0] = fmaxf(cmx[nn][0], acc[mt][nn][2 * hh]);
                    cmx[nn][1] = fmaxf(cmx[nn][1], acc[mt][nn][2 * hh + 1]);
                }
            }
        }
#pragma unroll
    for (int msk = 4; msk <= 16; msk <<= 1)
#pragma unroll
        for (int nn = 0; nn < 8; nn++) {
            cmx[nn][0] = fmaxf(cmx[nn][0], __shfl_xor_sync(0xffffffffu, cmx[nn][0], msk));
            cmx[nn][1] = fmaxf(cmx[nn][1], __shfl_xor_sync(0xffffffffu, cmx[nn][1], msk));
        }
    unsigned* sglb = (unsigned*)(sm + P1_GLB);
    if (lane < 4) {
#pragma unroll
        for (int nn = 0; nn < 8; nn++) {
            atomicMax(&sglb[nn * 8 + 2 * c + 0], enc_f(cmx[nn][0]));
            atomicMax(&sglb[nn * 8 + 2 * c + 1], enc_f(cmx[nn][1]));
        }
    }
    __syncthreads();
    if (tid < 64) atomicMax(&g_glb[tid], sglb[tid]);
}

// -------- kernel 4: phase 2 --------------------------------------------------
__global__ void __launch_bounds__(128)
k_phase2(const float* __restrict__ feat,
         const float* __restrict__ w3, const float* __restrict__ b3,
         const float* __restrict__ ln3g, const float* __restrict__ ln3b,
         const float* __restrict__ w4, int n) {
    extern __shared__ __align__(1024) char sm[];
    int tid = threadIdx.x, w = tid >> 5, lane = tid & 31, c = lane & 3;
    uint32_t smu = smem_u32(sm);

    float* stage = (float*)(sm + P2_STAGE);   // w3 top half fp32
    for (int q = tid; q < 4096; q += 128) stage[q] = w3[q];
    if (tid < 64) {
        ((float*)(sm + P2_GLBV))[tid] = dec_f(g_glb[tid]);
        ((float*)(sm + P2_LN3G))[tid] = ln3g[tid];
        ((float*)(sm + P2_LN3B))[tid] = ln3b[tid];
        ((float*)(sm + P2_W4))[tid]   = w4[tid];
    }
    __syncthreads();

    build_B(sm, P2_B_HI, P2_B_LO, stage, tid);

    // fold glb into bias
    if (tid < 64) {
        const float* glbv = (const float*)(sm + P2_GLBV);
        int j = tid;
        float a0 = b3[j], a1 = 0.f, a2 = 0.f, a3 = 0.f;
#pragma unroll
        for (int k = 0; k < 64; k += 4) {
            a0 = fmaf(glbv[k + 0], w3[(64 + k + 0) * 64 + j], a0);
            a1 = fmaf(glbv[k + 1], w3[(64 + k + 1) * 64 + j], a1);
            a2 = fmaf(glbv[k + 2], w3[(64 + k + 2) * 64 + j], a2);
            a3 = fmaf(glbv[k + 3], w3[(64 + k + 3) * 64 + j], a3);
        }
        ((float*)(sm + P2_GC))[j] = (a0 + a1) + (a2 + a3);
    }
    __syncthreads();

    // MMA: A fragments straight from scratch (fragment layout)
    float acc[2][8][4];
#pragma unroll
    for (int mt = 0; mt < 2; mt++)
#pragma unroll
        for (int nn = 0; nn < 8; nn++)
#pragma unroll
            for (int r = 0; r < 4; r++) acc[mt][nn][r] = 0.f;

    size_t sbase = ((size_t)blockIdx.x * 4 + w) * 8;
    uint32_t bhi = smu + P2_B_HI, blo = smu + P2_B_LO;
#pragma unroll
    for (int ks = 0; ks < 4; ks++) {
        uint4 H0v = g_scr_hi[(sbase + 0 + ks) * 32 + lane];
        uint4 H1v = g_scr_hi[(sbase + 4 + ks) * 32 + lane];
        uint32_t H0[4] = {H0v.x, H0v.y, H0v.z, H0v.w};
        uint32_t H1[4] = {H1v.x, H1v.y, H1v.z, H1v.w};
#pragma unroll
        for (int nn = 0; nn < 8; nn++) {
            uint32_t B[2];
            ldsm_x2t(B, b_addr(bhi, ks, nn, lane));
            mma16816(acc[0][nn], H0, B);
            mma16816(acc[1][nn], H1, B);
        }
#pragma unroll
        for (int nn = 0; nn < 8; nn++) {
            uint32_t B[2];
            ldsm_x2t(B, b_addr(blo, ks, nn, lane));
            mma16816(acc[0][nn], H0, B);
            mma16816(acc[1][nn], H1, B);
        }
        uint4 L0v = g_scr_lo[(sbase + 0 + ks) * 32 + lane];
        uint4 L1v = g_scr_lo[(sbase + 4 + ks) * 32 + lane];
        uint32_t L0[4] = {L0v.x, L0v.y, L0v.z, L0v.w};
        uint32_t L1[4] = {L1v.x, L1v.y, L1v.z, L1v.w};
#pragma unroll
        for (int nn = 0; nn < 8; nn++) {
            uint32_t B[2];
            ldsm_x2t(B, b_addr(bhi, ks, nn, lane));
            mma16816(acc[0][nn], L0, B);
            mma16816(acc[1][nn], L1, B);
        }
    }

    // epilogue: +gc, LN3+ReLU, logit, sigmoid
    float2 add2[8], g2[8], bb2[8], w42[8];
    {
        const float* pgc = (const float*)(sm + P2_GC);
        const float* pg = (const float*)(sm + P2_LN3G);
        const float* pbb = (const float*)(sm + P2_LN3B);
        const float* pw4 = (const float*)(sm + P2_W4);
#pragma unroll
        for (int nn = 0; nn < 8; nn++) {
            int col = nn * 8 + 2 * c;
            add2[nn] = *(const float2*)&pgc[col];
            g2[nn]   = *(const float2*)&pg[col];
            bb2[nn]  = *(const float2*)&pbb[col];
            w42[nn]  = *(const float2*)&pw4[col];
        }
    }
#pragma unroll
    for (int mt = 0; mt < 2; mt++)
#pragma unroll
        for (int nn = 0; nn < 8; nn++) {
            acc[mt][nn][0] += add2[nn].x; acc[mt][nn][1] += add2[nn].y;
            acc[mt][nn][2] += add2[nn].x; acc[mt][nn][3] += add2[nn].y;
        }
    ln_frag(acc, g2, bb2, true);

    float* s_w = (float*)(sm + P2_SW);
    int rq = lane >> 2;
#pragma unroll
    for (int mt = 0; mt < 2; mt++)
#pragma unroll
        for (int hh = 0; hh < 2; hh++) {
            float t = 0.f;
#pragma unroll
            for (int nn = 0; nn < 8; nn++)
                t = fmaf(acc[mt][nn][2 * hh], w42[nn].x,
                    fmaf(acc[mt][nn][2 * hh + 1], w42[nn].y, t));
            t += __shfl_xor_sync(0xffffffffu, t, 1);
            t += __shfl_xor_sync(0xffffffffu, t, 2);
            if (c == 0) {
                int lrow = 32 * w + 16 * mt + 8 * hh + rq;
                int grow = blockIdx.x * 128 + lrow;
                s_w[lrow] = (grow < n) ? (2.0f / (1.0f + __expf(-t))) : 0.f;
            }
        }
    __syncthreads();

    // feat accumulation: 2 row-groups x 64 float4 columns (D == 256)
    int cc = tid & 63;
    int g = tid >> 6;
    const float4* fp = (const float4*)feat;
    float4* spart = (float4*)(sm + P2_SPART);
    float4 facc = make_float4(0.f, 0.f, 0.f, 0.f);
    int rbase = blockIdx.x * 128 + g * 64;
    if (rbase + 64 <= n) {
#pragma unroll 8
        for (int ii = 0; ii < 64; ii++) {
            float4 v = fp[(size_t)(rbase + ii) * 64 + cc];
            float ww = s_w[g * 64 + ii];
            facc.x = fmaf(v.x, ww, facc.x);
            facc.y = fmaf(v.y, ww, facc.y);
            facc.z = fmaf(v.z, ww, facc.z);
            facc.w = fmaf(v.w, ww, facc.w);
        }
    } else {
#pragma unroll 8
        for (int ii = 0; ii < 64; ii++) {
            int r = rbase + ii;
            if (r < n) {
                float4 v = fp[(size_t)r * 64 + cc];
                float ww = s_w[g * 64 + ii];
                facc.x = fmaf(v.x, ww, facc.x);
                facc.y = fmaf(v.y, ww, facc.y);
                facc.z = fmaf(v.z, ww, facc.z);
                facc.w = fmaf(v.w, ww, facc.w);
            }
        }
    }
    spart[g * 64 + cc] = facc;
    __syncthreads();
    if (tid < 64) {
        float4 a = spart[tid];
        float4 b = spart[64 + tid];
        float4 r;
        r.x = a.x + b.x; r.y = a.y + b.y; r.z = a.z + b.z; r.w = a.w + b.w;
        ((float4*)g_out_part)[(size_t)blockIdx.x * 64 + tid] = r;
    }
}

// -------- kernel 5: mid reduction ------------------------------------------
__global__ void k_out_mid(int nb) {
    int b0 = blockIdx.x * 128;
    int bmax = nb - b0; if (bmax > 128) bmax = 128;
    int d = threadIdx.x;  // 256
    float a0 = 0.f, a1 = 0.f, a2 = 0.f, a3 = 0.f;
    int b = 0;
    for (; b + 4 <= bmax; b += 4) {
        a0 += g_out_part[(size_t)(b0 + b + 0) * 256 + d];
        a1 += g_out_part[(size_t)(b0 + b + 1) * 256 + d];
        a2 += g_out_part[(size_t)(b0 + b + 2) * 256 + d];
        a3 += g_out_part[(size_t)(b0 + b + 3) * 256 + d];
    }
    for (; b < bmax; b++)
        a0 += g_out_part[(size_t)(b0 + b) * 256 + d];
    g_out_part2[(size_t)blockIdx.x * 256 + d] = (a0 + a1) + (a2 + a3);
}

// -------- kernel 6: final ---------------------------------------------------
__global__ void k_out_final(float* __restrict__ out, int n, int nb2) {
    int d = threadIdx.x;
    float inv_n = 1.0f / (float)n;
    float s = 0.f;
    for (int b = 0; b < nb2; b++) s += g_out_part2[(size_t)b * 256 + d];
    out[d] = s * inv_n;
}

// -------- launch ------------------------------------------------------------
extern "C" void kernel_launch(void* const* d_in, const int* in_sizes, int n_in,
                              void* d_out, int out_size) {
    const float* feat = (const float*)d_in[0];
    const float* xyz  = (const float*)d_in[1];
    const float* w1   = (const float*)d_in[2];
    const float* b1   = (const float*)d_in[3];
    const float* ln1g = (const float*)d_in[4];
    const float* ln1b = (const float*)d_in[5];
    const float* w2   = (const float*)d_in[6];
    const float* b2   = (const float*)d_in[7];
    const float* ln2g = (const float*)d_in[8];
    const float* ln2b = (const float*)d_in[9];
    const float* w3   = (const float*)d_in[10];
    const float* b3   = (const float*)d_in[11];
    const float* ln3g = (const float*)d_in[12];
    const float* ln3b = (const float*)d_in[13];
    const float* w4   = (const float*)d_in[14];

    int n = in_sizes[1] / 3;
    int NB = (n + 127) / 128;
    int NB2 = (NB + 127) / 128;

    static int attr_done = 0;
    if (!attr_done) {
        cudaFuncSetAttribute(k_phase1, cudaFuncAttributeMaxDynamicSharedMemorySize, P1_DSM);
        cudaFuncSetAttribute(k_phase2, cudaFuncAttributeMaxDynamicSharedMemorySize, P2_DSM);
        attr_done = 1;
    }

    k_stats<<<STATS_BLOCKS, 256>>>(xyz, n);
    k_stats_final<<<1, 256>>>(n);
    k_phase1<<<NB, 128, P1_DSM>>>(xyz, w1, b1, ln1g, ln1b, w2, b2, ln2g, ln2b, n);
    k_phase2<<<NB, 128, P2_DSM>>>(feat, w3, b3, ln3g, ln3b, w4, n);
    k_out_mid<<<NB2, 256>>>(NB);
    k_out_final<<<1, 256>>>((float*)d_out, n, NB2);
}